// round 1
// baseline (speedup 1.0000x reference)
#include <cuda_runtime.h>

// iDDPMPrecond: outputs (c_skip=1, c_out=-s, c_in=1/sqrt(s^2+1), c_noise=M-1-argmin_j|s-u_j|)
// u is monotonically decreasing (u[0] max, u[M]=0) -> binary search instead of 1001-scan.

__global__ void precond_kernel(const float* __restrict__ sigma,
                               const float* __restrict__ u,
                               float* __restrict__ out,
                               int B, int M, int skip_count)
{
    extern __shared__ float su[];  // M+1 entries
    const int nU = M + 1;
    for (int i = threadIdx.x; i < nU; i += blockDim.x) su[i] = u[i];
    __syncthreads();

    int tid = blockIdx.x * blockDim.x + threadIdx.x;

    // c_skip region (scalar or broadcast, skip_count elements of 1.0f)
    if (tid < skip_count) out[tid] = 1.0f;

    if (tid >= B) return;

    float s = sigma[tid];
    out[skip_count + tid]     = -s;                    // c_out
    out[skip_count + B + tid] = rsqrtf(s * s + 1.0f);  // c_in

    // argmin_j |s - su[j]| with first-occurrence tie-breaking, su decreasing.
    int j;
    if (s >= su[0]) {
        j = 0;
    } else {
        // first index j in [1, M] with su[j] <= s  (exists: su[M] = 0 <= s)
        int lo = 1, hi = M;
        while (lo < hi) {
            int mid = (lo + hi) >> 1;
            if (su[mid] <= s) hi = mid; else lo = mid + 1;
        }
        j = lo;
        float d_lo = s - su[j];        // >= 0
        float d_hi = su[j - 1] - s;    // >  0
        if (d_hi <= d_lo) j = j - 1;   // tie -> smaller index (argmin semantics)
        // walk back over any f32-cast duplicates so we return the FIRST index
        // achieving the minimum distance (matches jnp.argmin exactly)
        while (j > 0 && su[j - 1] == su[j]) j--;
    }
    out[skip_count + 2 * B + tid] = (float)(M - 1 - j);  // c_noise
}

extern "C" void kernel_launch(void* const* d_in, const int* in_sizes, int n_in,
                              void* d_out, int out_size)
{
    // inputs per metadata order: x (unused), sigma, u, M
    const float* sigma = (const float*)d_in[1];
    const float* u     = (const float*)d_in[2];
    const int B  = in_sizes[1];
    const int nU = in_sizes[2];
    const int M  = nU - 1;

    // Flattened tuple layout: [c_skip (skip elems)] [c_out B] [c_in B] [c_noise B]
    int skip = out_size - 3 * B;
    if (skip < 0) skip = 0;

    const int threads = 256;
    const int blocks  = (B + threads - 1) / threads;
    precond_kernel<<<blocks, threads, nU * sizeof(float)>>>(
        sigma, u, (float*)d_out, B, M, skip);
}